// round 11
// baseline (speedup 1.0000x reference)
#include <cuda_runtime.h>

#define NW 10
#define DIM 1024
#define WARPS_PER_BLK 4

typedef unsigned long long u64;

// ---- packed f32x2 primitives ----
__device__ __forceinline__ u64 pk(float x, float y) {
    u64 r; asm("mov.b64 %0,{%1,%2};" : "=l"(r) : "f"(x), "f"(y)); return r;
}
__device__ __forceinline__ u64 pkb(float x) { return pk(x, x); }
__device__ __forceinline__ void upk(u64 a, float& x, float& y) {
    asm("mov.b64 {%0,%1},%2;" : "=f"(x), "=f"(y) : "l"(a));
}
__device__ __forceinline__ float hadd(u64 a) {
    float x, y; upk(a, x, y); return x + y;
}
__device__ __forceinline__ float hdiff(u64 a) {
    float x, y; upk(a, x, y); return x - y;
}
__device__ __forceinline__ u64 f2fma(u64 a, u64 b, u64 c) {
    u64 d; asm("fma.rn.f32x2 %0,%1,%2,%3;" : "=l"(d) : "l"(a), "l"(b), "l"(c)); return d;
}
__device__ __forceinline__ u64 f2mul(u64 a, u64 b) {
    u64 d; asm("mul.rn.f32x2 %0,%1,%2;" : "=l"(d) : "l"(a), "l"(b)); return d;
}
__device__ __forceinline__ u64 f2add(u64 a, u64 b) {
    u64 d; asm("add.rn.f32x2 %0,%1,%2;" : "=l"(d) : "l"(a), "l"(b)); return d;
}
__device__ __forceinline__ u64 f2sub(u64 a, u64 b) {
    u64 d; asm("sub.rn.f32x2 %0,%1,%2;" : "=l"(d) : "l"(a), "l"(b)); return d;
}
__device__ __forceinline__ u64 swp(u64 a) {      // (x,y)->(y,x)
    float x, y; upk(a, x, y); return pk(y, x);
}
__device__ __forceinline__ u64 ldsv(const u64* p) {   // no cross-gate hoisting
    return *(const volatile u64*)p;
}

// XOR swizzle for conflict-free 32x32 8-byte transpose through shared memory.
__device__ __forceinline__ int swz(int idx) {
    return (idx & 0x3E0) | (((idx >> 5) ^ idx) & 31);
}

// Real RY butterfly on register bit K (packed complex amplitudes):
//   n0 = c a0 - s a1 ; n1 = s a0 + c a1     (c,s broadcast-packed in shared)
template<int K>
__device__ __forceinline__ void ryg(u64* a, const u64* cf) {
    const u64 cc = ldsv(cf + 0), ss = ldsv(cf + 1), nss = ldsv(cf + 2);
#pragma unroll
    for (int p = 0; p < 16; ++p) {
        const int m0 = ((p >> K) << (K + 1)) | (p & ((1 << K) - 1));
        const int m1 = m0 | (1 << K);
        u64 n0 = f2fma(cc, a[m0], f2mul(nss, a[m1]));
        u64 n1 = f2fma(ss, a[m0], f2mul(cc,  a[m1]));
        a[m0] = n0; a[m1] = n1;
    }
}

// In-register X-coherence sum with Dphi phase classes.
// HB = halving bit mask, CB = class bit mask, PM = partner xor mask.
// Accumulates P=(Re-cross), Q=(Im-cross parts) per class; combines with
// class angles: contribution = sum_pairs Re(e^{i theta} chi_j^* chi_k).
template<int HB, int CB, int PM>
__device__ __forceinline__ float xwire(const u64* a, float cp, float sp,
                                       float cm, float sm) {
    u64 Pp = 0, Qp = 0, Pm = 0, Qm = 0;
#pragma unroll
    for (int r = 0; r < 32; ++r) {
        if (!(r & HB)) {
            u64 k = a[r ^ PM], ks = swp(k);
            if (r & CB) { Pm = f2fma(a[r], k, Pm); Qm = f2fma(a[r], ks, Qm); }
            else        { Pp = f2fma(a[r], k, Pp); Qp = f2fma(a[r], ks, Qp); }
        }
    }
    return cp * hadd(Pp) - sp * hdiff(Qp) + cm * hadd(Pm) - sm * hdiff(Qm);
}

// ============================================================================
// Layer 1 ZYZ-factored: layer1 = Dphi * (prod_q RY_q(2 Theta_q)) * Dlam.
//  - Dlam folded into the load (separable phase tables zr[32], zt[32]).
//  - RY gates: real butterflies (4 packed ops / butterfly).
//  - Dphi folded into the X observables as per-pair phase classes.
// Layer-2 RY + CNOT ring folded into observables (R7 derivation):
//  E_q = cz_q * <Z_q> + cxw_q * X_q ; Z on |chi|^2 (phase-free), X with classes.
// ============================================================================

__global__ __launch_bounds__(128, 4)
void qsa10_kernel(const float* __restrict__ x,
                  const float* __restrict__ rx0,
                  const float* __restrict__ ry0,
                  const float* __restrict__ ry1,
                  float* __restrict__ out)
{
    __shared__ u64 buf[WARPS_PER_BLK][DIM];   // 8 KB per warp
    __shared__ u64 cry[NW][3];                // packed RY coeffs (c, s, -s)
    __shared__ u64 zr[32], zt[32];            // Dlam phase tables (cos,sin)
    __shared__ float sphi[NW], slam[NW];
    __shared__ float cthp[NW], sthp[NW], cthm[NW], sthm[NW];  // X class angles
    __shared__ float c9w[4], s9w[4];          // wire-9 (3-bit mask) classes
    __shared__ float cz[NW], cxw[NW];

    const int tid = threadIdx.x;

    // ---- Prep stage 1: per-wire ZYZ decomposition ----
    if (tid < NW) {
        float s, c, s0, c0, s1, c1;
        sincosf(0.5f * rx0[tid], &s,  &c);
        sincosf(0.5f * ry0[tid], &s0, &c0);
        sincosf(0.5f * ry1[tid], &s1, &c1);
        // M = RY(ry0)*RX(rx0) = [[a, b], [-conj(b), conj(a)]]
        const float ar =  c0 * c;
        const float ai =  s0 * s;
        const float br = -s0 * c;
        const float bi = -c0 * s;
        // ZYZ: M = RZ(phi) RY(2T) RZ(lam); cosT=|a|, sinT=|b|,
        //      phi = -(arg(a)+arg(-b)), lam = arg(-b)-arg(a).
        const float uu = atan2f(ai, ar);
        const float vv = atan2f(-bi, -br);
        sphi[tid] = -(uu + vv);
        slam[tid] = vv - uu;
        const float cT = sqrtf(ar * ar + ai * ai);
        const float sT = sqrtf(br * br + bi * bi);
        cry[tid][0] = pkb(cT);
        cry[tid][1] = pkb(sT);
        cry[tid][2] = pkb(-sT);
        cz[tid]  = c1 * c1 - s1 * s1;   // cos(theta1)
        cxw[tid] = -4.f * c1 * s1;      // -2 sin(theta1), pair-once accumulation
    }
    __syncthreads();

    // ---- Prep stage 2: phase tables and X class angles ----
    if (tid < 32) {
        // Dlam phase for 10-bit index j=(r<<5)|t: wires 0-4 <-> r bits 4-0,
        // wires 5-9 <-> t bits 4-0. Global phase dropped (cancels in observables).
        float angr = 0.f, angt = 0.f;
#pragma unroll
        for (int k = 0; k < 5; ++k)  if ((tid >> (4 - k)) & 1) angr += slam[k];
#pragma unroll
        for (int k = 5; k < 10; ++k) if ((tid >> (9 - k)) & 1) angt += slam[k];
        float sa, ca;
        sincosf(angr, &sa, &ca); zr[tid] = pk(ca, sa);
        sincosf(angt, &sa, &ca); zt[tid] = pk(ca, sa);
    }
    if (tid < 9) {
        // Wires 0..8: class angles theta+- = phi_q +- phi_{q+1}
        // (wire 4 special: theta = phi5 + phi4*(1-2 j5) -> minus class = phi5-phi4)
        const float p1 = sphi[tid], p2 = sphi[tid + 1];
        const float tp = p1 + p2;
        const float tm = (tid == 4) ? (p2 - p1) : (p1 - p2);
        float sa, ca;
        sincosf(tp, &sa, &ca); cthp[tid] = ca; sthp[tid] = sa;
        sincosf(tm, &sa, &ca); cthm[tid] = ca; sthm[tid] = sa;
    }
    if (tid == 9) {
        // Wire 9 (m bits {9,8,0}): theta = phi9 + phi0(1-2 j9) + phi1(1-2 j8),
        // class idx = (j9<<1)|j8.
#pragma unroll
        for (int k = 0; k < 4; ++k) {
            float th = sphi[9] + sphi[0] * (1.f - 2.f * ((k >> 1) & 1))
                                + sphi[1] * (1.f - 2.f * (k & 1));
            float sa, ca; sincosf(th, &sa, &ca);
            c9w[k] = ca; s9w[k] = sa;
        }
    }

    const int w = tid >> 5;
    const int t = tid & 31;
    const int n = blockIdx.x * WARPS_PER_BLK + w;   // state 0..4095
    u64* sb = buf[w];

    // ---- Load (LA: i=(r<<5)|t) + packed sumsq ----
    u64 a[32];
    const float* xr = x + (size_t)n * DIM;
    u64 sq = 0ull;
#pragma unroll
    for (int r = 0; r < 32; ++r) {
        a[r] = pkb(xr[(r << 5) + t]);
        sq = f2fma(a[r], a[r], sq);
    }
    float sumsq, dmy;
    upk(sq, sumsq, dmy);
#pragma unroll
    for (int off = 16; off; off >>= 1)
        sumsq += __shfl_xor_sync(0xffffffffu, sumsq, off);
    const float inv = 1.f / fmaxf(sqrtf(sumsq), 1e-12f);
    __syncthreads();    // stage-2 tables visible to all warps

    // ---- Init: a[j] = v_j * inv * zr(r) * zt(t)  (Dlam applied at load) ----
    {
        float ctt, stt;
        upk(zt[t], ctt, stt);
        const u64 T1 = pk(ctt * inv, ctt * inv);
        const u64 T2 = pk(-stt * inv, stt * inv);
#pragma unroll
        for (int r = 0; r < 32; ++r) {
            u64 z = zr[r];
            a[r] = f2mul(a[r], f2fma(z, T1, f2mul(swp(z), T2)));
        }
    }

    // ---- Phase A: RY on wires 0..4 (wire q -> reg bit K=4-q) ----
    ryg<4>(a, cry[0]);
    ryg<3>(a, cry[1]);
    ryg<2>(a, cry[2]);
    ryg<1>(a, cry[3]);
    ryg<0>(a, cry[4]);

    // ---- Remap LA -> LB (transpose) ----
    __syncwarp();
#pragma unroll
    for (int r = 0; r < 32; ++r) sb[swz((r << 5) | t)] = a[r];
    __syncwarp();
#pragma unroll
    for (int r = 0; r < 32; ++r) a[r] = sb[swz((t << 5) | r)];

    // ---- Phase B: RY on wires 5..9 (wire q -> reg bit K=9-q) ----
    ryg<4>(a, cry[5]);
    ryg<3>(a, cry[6]);
    ryg<2>(a, cry[7]);
    ryg<1>(a, cry[8]);
    ryg<0>(a, cry[9]);

    // ======================= Epilogue on chi (LB: j=(t<<5)|r) ================

    // Z-part (phase-invariant): tot + 5 signed r-sums via quad butterflies.
    u64 tot = 0, S10 = 0, S18 = 0, S1C = 0, S1E = 0, S1F = 0;
#pragma unroll
    for (int r = 0; r < 32; r += 4) {
        u64 q0 = f2mul(a[r],     a[r]);
        u64 q1 = f2mul(a[r + 1], a[r + 1]);
        u64 q2 = f2mul(a[r + 2], a[r + 2]);
        u64 q3 = f2mul(a[r + 3], a[r + 3]);
        u64 s01 = f2add(q0, q1), s23 = f2add(q2, q3);
        u64 d01 = f2sub(q0, q1), d23 = f2sub(q2, q3);
        u64 ss = f2add(s01, s23);
        u64 sd = f2sub(s01, s23);
        u64 df = f2sub(d01, d23);
        const int pq = ((r >> 4) ^ (r >> 3) ^ (r >> 2)) & 1;
        tot = f2add(tot, ss);
        S10 = (r & 0x10)                  ? f2sub(S10, ss) : f2add(S10, ss);
        S18 = (((r >> 4) ^ (r >> 3)) & 1) ? f2sub(S18, ss) : f2add(S18, ss);
        S1C = pq ? f2sub(S1C, ss) : f2add(S1C, ss);
        S1E = pq ? f2sub(S1E, sd) : f2add(S1E, sd);
        S1F = pq ? f2sub(S1F, df) : f2add(S1F, df);
    }
    const float tot_s = hadd(tot);
    const float s10 = hadd(S10), s18 = hadd(S18), s1C = hadd(S1C);
    const float s1E = hadd(S1E), s1F = hadd(S1F);

    // X in-register wires 5..8 (LB r-bits), with Dphi phase classes.
    const float x5 = xwire<0x10, 0x08, 0x18>(a, cthp[5], sthp[5], cthm[5], sthm[5]);
    const float x6 = xwire<0x08, 0x04, 0x0C>(a, cthp[6], sthp[6], cthm[6], sthm[6]);
    const float x7 = xwire<0x04, 0x02, 0x06>(a, cthp[7], sthp[7], cthm[7], sthm[7]);
    const float x8 = xwire<0x02, 0x01, 0x03>(a, cthp[8], sthp[8], cthm[8], sthm[8]);

    // Straddler w4 (m bits {5,4} = {t0, r4}): pairs (t, r<16)<->(t^1, r+16).
    // Class constant per thread: j5 = t0.
    float x4, x9;
    {
        u64 P = 0, Q = 0;
#pragma unroll
        for (int r = 0; r < 16; ++r) {
            u64 k = __shfl_xor_sync(0xffffffffu, a[r + 16], 1);
            P = f2fma(a[r], k, P);
            Q = f2fma(a[r], swp(k), Q);
        }
        const float c4 = (t & 1) ? cthm[4] : cthp[4];
        const float s4 = (t & 1) ? sthm[4] : sthp[4];
        x4 = c4 * hadd(P) - s4 * hdiff(Q);
    }
    // Straddler w9 (m bits {9,8,0} = {t4, t3, r0}): pairs (t, r even)<->(t^0x18, r+1).
    // Class constant per thread: idx = (t4<<1)|t3.
    {
        u64 P = 0, Q = 0;
#pragma unroll
        for (int r = 0; r < 32; r += 2) {
            u64 k = __shfl_xor_sync(0xffffffffu, a[r + 1], 0x18);
            P = f2fma(a[r], k, P);
            Q = f2fma(a[r], swp(k), Q);
        }
        const int i9 = (t >> 3) & 3;
        x9 = c9w[i9] * hadd(P) - s9w[i9] * hdiff(Q);
    }

    // ---- Transpose LB -> LA for wires 0..3 X-terms ----
    __syncwarp();
#pragma unroll
    for (int r = 0; r < 32; ++r) sb[swz((t << 5) | r)] = a[r];
    __syncwarp();
#pragma unroll
    for (int r = 0; r < 32; ++r) a[r] = sb[swz((r << 5) | t)];

    // X in-register wires 0..3 (LA r-bits = j9..j5), same masks/classes.
    const float x0 = xwire<0x10, 0x08, 0x18>(a, cthp[0], sthp[0], cthm[0], sthm[0]);
    const float x1 = xwire<0x08, 0x04, 0x0C>(a, cthp[1], sthp[1], cthm[1], sthm[1]);
    const float x2 = xwire<0x04, 0x02, 0x06>(a, cthp[2], sthp[2], cthm[2], sthm[2]);
    const float x3 = xwire<0x02, 0x01, 0x03>(a, cthp[3], sthp[3], cthm[3], sthm[3]);

    // Thread-parity signs for the Z parts (t-masks from M_b >> 5).
    const float sgA = (__popc(t & 0x0F) & 1) ? -1.f : 1.f;   // wire 0
    const float sgB = (__popc(t & 0x18) & 1) ? -1.f : 1.f;   // wire 1
    const float sgC = (__popc(t & 0x1C) & 1) ? -1.f : 1.f;   // wire 2
    const float sgD = (__popc(t & 0x1E) & 1) ? -1.f : 1.f;   // wire 3
    const float sgE = (__popc(t & 0x1F) & 1) ? -1.f : 1.f;   // wires 4..9

    // Combine: E_q = cz[q] * Z_q + cxw[q] * X_q  (per-thread partials).
    float e[NW];
    e[0] = cz[0] * (sgA * s1F)   + cxw[0] * x0;
    e[1] = cz[1] * (sgB * tot_s) + cxw[1] * x1;
    e[2] = cz[2] * (sgC * tot_s) + cxw[2] * x2;
    e[3] = cz[3] * (sgD * tot_s) + cxw[3] * x3;
    e[4] = cz[4] * (sgE * tot_s) + cxw[4] * x4;
    e[5] = cz[5] * (sgE * s10)   + cxw[5] * x5;
    e[6] = cz[6] * (sgE * s18)   + cxw[6] * x6;
    e[7] = cz[7] * (sgE * s1C)   + cxw[7] * x7;
    e[8] = cz[8] * (sgE * s1E)   + cxw[8] * x8;
    e[9] = cz[9] * (sgE * s1F)   + cxw[9] * x9;

    // Packed warp reduction of 10 values as 5 u64.
    u64 vp[5];
#pragma unroll
    for (int j = 0; j < 5; ++j) vp[j] = pk(e[2 * j], e[2 * j + 1]);
#pragma unroll
    for (int off = 16; off; off >>= 1) {
#pragma unroll
        for (int j = 0; j < 5; ++j)
            vp[j] = f2add(vp[j], __shfl_xor_sync(0xffffffffu, vp[j], off));
    }
    if (t == 0) {
#pragma unroll
        for (int j = 0; j < 5; ++j) {
            float vx, vy;
            upk(vp[j], vx, vy);
            out[(size_t)n * NW + 2 * j]     = vx;
            out[(size_t)n * NW + 2 * j + 1] = vy;
        }
    }
}

extern "C" void kernel_launch(void* const* d_in, const int* in_sizes, int n_in,
                              void* d_out, int out_size) {
    const float* x   = (const float*)d_in[0];
    const float* rx0 = (const float*)d_in[1];
    const float* ry0 = (const float*)d_in[2];
    const float* ry1 = (const float*)d_in[3];
    float* out = (float*)d_out;
    const int n_states = in_sizes[0] / DIM;            // 4096
    qsa10_kernel<<<n_states / WARPS_PER_BLK, 32 * WARPS_PER_BLK>>>(x, rx0, ry0, ry1, out);
}

// round 12
// speedup vs baseline: 1.1329x; 1.1329x over previous
#include <cuda_runtime.h>

#define NW 10
#define DIM 1024
#define WARPS_PER_BLK 4

typedef unsigned long long u64;

// ---- packed f32x2 primitives ----
__device__ __forceinline__ u64 pk(float x, float y) {
    u64 r; asm("mov.b64 %0,{%1,%2};" : "=l"(r) : "f"(x), "f"(y)); return r;
}
__device__ __forceinline__ u64 pkb(float x) { return pk(x, x); }
__device__ __forceinline__ void upk(u64 a, float& x, float& y) {
    asm("mov.b64 {%0,%1},%2;" : "=f"(x), "=f"(y) : "l"(a));
}
__device__ __forceinline__ float hadd(u64 a) {
    float x, y; upk(a, x, y); return x + y;
}
__device__ __forceinline__ u64 f2fma(u64 a, u64 b, u64 c) {
    u64 d; asm("fma.rn.f32x2 %0,%1,%2,%3;" : "=l"(d) : "l"(a), "l"(b), "l"(c)); return d;
}
__device__ __forceinline__ u64 f2mul(u64 a, u64 b) {
    u64 d; asm("mul.rn.f32x2 %0,%1,%2;" : "=l"(d) : "l"(a), "l"(b)); return d;
}
__device__ __forceinline__ u64 f2add(u64 a, u64 b) {
    u64 d; asm("add.rn.f32x2 %0,%1,%2;" : "=l"(d) : "l"(a), "l"(b)); return d;
}
__device__ __forceinline__ u64 f2sub(u64 a, u64 b) {
    u64 d; asm("sub.rn.f32x2 %0,%1,%2;" : "=l"(d) : "l"(a), "l"(b)); return d;
}
__device__ __forceinline__ u64 swp(u64 a) {      // (x,y)->(y,x)
    float x, y; upk(a, x, y); return pk(y, x);
}
__device__ __forceinline__ u64 ldsv(const u64* p) {   // no cross-gate hoisting
    return *(const volatile u64*)p;
}

// XOR swizzle for conflict-free 32x32 8-byte transpose through shared memory.
__device__ __forceinline__ int swz(int idx) {
    return (idx & 0x3E0) | (((idx >> 5) ^ idx) & 31);
}

// ---- precomputed coefficient tables (written by qsa_prep) ----
__device__ u64 g_cry[NW * 3];      // RY gate coeffs (c, s, -s) broadcast-packed
__device__ u64 g_lamR[32];         // Dlam r-part (cos, sin)   [LA init]
__device__ u64 g_lamT[32];         // Dlam t-part (cos, sin)   [LA init]
__device__ u64 g_phiT[32];         // Dphi t-part (cos, sin)   [LB apply]
__device__ u64 g_phiRc[32];        // Dphi r-part (c, c)
__device__ u64 g_phiRs[32];        // Dphi r-part (-s, s)
__device__ float g_cz[NW], g_cxw[NW];

// Prep kernel: ZYZ decomposition + all phase tables, once.
__global__ void qsa_prep(const float* __restrict__ rx0,
                         const float* __restrict__ ry0,
                         const float* __restrict__ ry1) {
    __shared__ float sphi[NW], slam[NW];
    const int tid = threadIdx.x;
    if (tid < NW) {
        float s, c, s0, c0, s1, c1;
        sincosf(0.5f * rx0[tid], &s,  &c);
        sincosf(0.5f * ry0[tid], &s0, &c0);
        sincosf(0.5f * ry1[tid], &s1, &c1);
        // M = RY(ry0)*RX(rx0) = [[a, b], [-conj(b), conj(a)]]
        const float ar =  c0 * c;
        const float ai =  s0 * s;
        const float br = -s0 * c;
        const float bi = -c0 * s;
        // ZYZ: M = RZ(phi) RY(2T) RZ(lam) (conventions validated in R10)
        const float uu = atan2f(ai, ar);
        const float vv = atan2f(-bi, -br);
        sphi[tid] = -(uu + vv);
        slam[tid] = vv - uu;
        const float cT = sqrtf(ar * ar + ai * ai);
        const float sT = sqrtf(br * br + bi * bi);
        g_cry[tid * 3 + 0] = pkb(cT);
        g_cry[tid * 3 + 1] = pkb(sT);
        g_cry[tid * 3 + 2] = pkb(-sT);
        g_cz[tid]  = c1 * c1 - s1 * s1;
        g_cxw[tid] = -4.f * c1 * s1;       // half-sum X accumulation
    }
    __syncthreads();
    // Separable phase tables over a 5-bit index (tid = r or t).
    // LA (init): i=(r<<5)|t, wires 0-4 <-> r bits 4-0, wires 5-9 <-> t bits 4-0.
    // LB (apply): j=(t<<5)|r, wires 0-4 <-> t bits 4-0, wires 5-9 <-> r bits 4-0.
    float aLr = 0.f, aLt = 0.f, aPt = 0.f, aPr = 0.f;
#pragma unroll
    for (int k = 0; k < 5; ++k)
        if ((tid >> (4 - k)) & 1) { aLr += slam[k]; aPt += sphi[k]; }
#pragma unroll
    for (int k = 5; k < 10; ++k)
        if ((tid >> (9 - k)) & 1) { aLt += slam[k]; aPr += sphi[k]; }
    float sa, ca;
    sincosf(aLr, &sa, &ca); g_lamR[tid] = pk(ca, sa);
    sincosf(aLt, &sa, &ca); g_lamT[tid] = pk(ca, sa);
    sincosf(aPt, &sa, &ca); g_phiT[tid] = pk(ca, sa);
    sincosf(aPr, &sa, &ca); g_phiRc[tid] = pkb(ca); g_phiRs[tid] = pk(-sa, sa);
}

// Real RY butterfly on register bit K (packed complex amplitudes).
template<int K>
__device__ __forceinline__ void ryg(u64* a, const u64* cf) {
    const u64 cc = ldsv(cf + 0), ss = ldsv(cf + 1), nss = ldsv(cf + 2);
#pragma unroll
    for (int p = 0; p < 16; ++p) {
        const int m0 = ((p >> K) << (K + 1)) | (p & ((1 << K) - 1));
        const int m1 = m0 | (1 << K);
        u64 n0 = f2fma(cc, a[m0], f2mul(nss, a[m1]));
        u64 n1 = f2fma(ss, a[m0], f2mul(cc,  a[m1]));
        a[m0] = n0; a[m1] = n1;
    }
}

__global__ __launch_bounds__(128, 4)
void qsa11_kernel(const float* __restrict__ x, float* __restrict__ out)
{
    __shared__ u64 buf[WARPS_PER_BLK][DIM];   // 8 KB per warp
    __shared__ u64 cry[NW][3];
    __shared__ u64 lamR[32], phiRc[32], phiRs[32];
    __shared__ float cz[NW], cxw[NW];

    const int tid = threadIdx.x;
    if (tid < 32) {
        lamR[tid]  = g_lamR[tid];
        phiRc[tid] = g_phiRc[tid];
        phiRs[tid] = g_phiRs[tid];
        if (tid < 30) (&cry[0][0])[tid] = g_cry[tid];
        if (tid < NW) { cz[tid] = g_cz[tid]; cxw[tid] = g_cxw[tid]; }
    }
    __syncthreads();

    const int w = tid >> 5;
    const int t = tid & 31;
    const int n = blockIdx.x * WARPS_PER_BLK + w;   // state 0..4095
    u64* sb = buf[w];

    // ---- Load (LA: i=(r<<5)|t) + packed sumsq ----
    u64 a[32];
    const float* xr = x + (size_t)n * DIM;
    u64 sq = 0ull;
#pragma unroll
    for (int r = 0; r < 32; ++r) {
        a[r] = pkb(xr[(r << 5) + t]);
        sq = f2fma(a[r], a[r], sq);
    }
    float sumsq, dmy;
    upk(sq, sumsq, dmy);
#pragma unroll
    for (int off = 16; off; off >>= 1)
        sumsq += __shfl_xor_sync(0xffffffffu, sumsq, off);
    const float inv = 1.f / fmaxf(sqrtf(sumsq), 1e-12f);

    // ---- Init: a[i] = v * inv * e^{i lam(i)}  (input is real -> plain mul) ----
    {
        float ct, st;
        upk(g_lamT[t], ct, st);
        const u64 T1 = pkb(ct * inv);
        const u64 T2 = pk(-st * inv, st * inv);
#pragma unroll
        for (int r = 0; r < 32; ++r) {
            u64 z = ldsv(lamR + r);
            a[r] = f2mul(a[r], f2fma(z, T1, f2mul(swp(z), T2)));
        }
    }

    // ---- Phase A: RY on wires 0..4 (wire q -> reg bit K=4-q) ----
    ryg<4>(a, cry[0]);
    ryg<3>(a, cry[1]);
    ryg<2>(a, cry[2]);
    ryg<1>(a, cry[3]);
    ryg<0>(a, cry[4]);

    // ---- Remap LA -> LB (transpose) ----
    __syncwarp();
#pragma unroll
    for (int r = 0; r < 32; ++r) sb[swz((r << 5) | t)] = a[r];
    __syncwarp();
#pragma unroll
    for (int r = 0; r < 32; ++r) a[r] = sb[swz((t << 5) | r)];

    // ---- Phase B: RY on wires 5..9 (wire q -> reg bit K=9-q) ----
    ryg<4>(a, cry[5]);
    ryg<3>(a, cry[6]);
    ryg<2>(a, cry[7]);
    ryg<1>(a, cry[8]);
    ryg<0>(a, cry[9]);

    // ---- Apply Dphi (separable in LB: t-part wires 0-4, r-part wires 5-9) ----
    {
        float cpt, spt;
        upk(g_phiT[t], cpt, spt);
        const u64 T1b = pkb(cpt);
        const u64 T2b = pk(-spt, spt);
#pragma unroll
        for (int r = 0; r < 32; ++r) {
            u64 v = f2fma(a[r], ldsv(phiRc + r), f2mul(swp(a[r]), ldsv(phiRs + r)));
            a[r] = f2fma(v, T1b, f2mul(swp(v), T2b));
        }
    }

    // ======================= Epilogue on psi (LB: j=(t<<5)|r) ================
    // (identical to the validated R9 epilogue)

    // Z-part: tot + 5 signed r-sums via quad butterflies.
    u64 tot = 0, S10 = 0, S18 = 0, S1C = 0, S1E = 0, S1F = 0;
#pragma unroll
    for (int r = 0; r < 32; r += 4) {
        u64 q0 = f2mul(a[r],     a[r]);
        u64 q1 = f2mul(a[r + 1], a[r + 1]);
        u64 q2 = f2mul(a[r + 2], a[r + 2]);
        u64 q3 = f2mul(a[r + 3], a[r + 3]);
        u64 s01 = f2add(q0, q1), s23 = f2add(q2, q3);
        u64 d01 = f2sub(q0, q1), d23 = f2sub(q2, q3);
        u64 ss = f2add(s01, s23);
        u64 sd = f2sub(s01, s23);
        u64 df = f2sub(d01, d23);
        const int pq = ((r >> 4) ^ (r >> 3) ^ (r >> 2)) & 1;
        tot = f2add(tot, ss);
        S10 = (r & 0x10)                  ? f2sub(S10, ss) : f2add(S10, ss);
        S18 = (((r >> 4) ^ (r >> 3)) & 1) ? f2sub(S18, ss) : f2add(S18, ss);
        S1C = pq ? f2sub(S1C, ss) : f2add(S1C, ss);
        S1E = pq ? f2sub(S1E, sd) : f2add(S1E, sd);
        S1F = pq ? f2sub(S1F, df) : f2add(S1F, df);
    }
    const float tot_s = hadd(tot);
    const float s10 = hadd(S10), s18 = hadd(S18), s1C = hadd(S1C);
    const float s1E = hadd(S1E), s1F = hadd(S1F);

    // X in-register wires 5..8 (partners r^0x18, r^0xC, r^6, r^3), half-sums.
    u64 X5 = 0, X6 = 0, X7 = 0, X8 = 0;
#pragma unroll
    for (int r = 0; r < 32; ++r) {
        if (!(r & 0x10)) X5 = f2fma(a[r], a[r ^ 0x18], X5);
        if (!(r & 0x08)) X6 = f2fma(a[r], a[r ^ 0x0C], X6);
        if (!(r & 0x04)) X7 = f2fma(a[r], a[r ^ 0x06], X7);
        if (!(r & 0x02)) X8 = f2fma(a[r], a[r ^ 0x03], X8);
    }
    const float x5 = hadd(X5), x6 = hadd(X6), x7 = hadd(X7), x8 = hadd(X8);

    // Straddler X wires, half-sums:
    //  w4 (m=0x30): pairs (t, r<16) <-> (t^1, r+16)
    //  w9 (m=0x301): pairs (t, r even) <-> (t^0x18, r+1)
    u64 X4 = 0, X9 = 0;
#pragma unroll
    for (int r = 0; r < 16; ++r) {
        u64 p4 = __shfl_xor_sync(0xffffffffu, a[r + 16], 1);
        X4 = f2fma(a[r], p4, X4);
    }
#pragma unroll
    for (int r = 0; r < 32; r += 2) {
        u64 p9 = __shfl_xor_sync(0xffffffffu, a[r + 1], 0x18);
        X9 = f2fma(a[r], p9, X9);
    }
    const float x4 = hadd(X4), x9 = hadd(X9);

    // ---- Transpose LB -> LA for wires 0..3 X-terms ----
    __syncwarp();
#pragma unroll
    for (int r = 0; r < 32; ++r) sb[swz((t << 5) | r)] = a[r];
    __syncwarp();
#pragma unroll
    for (int r = 0; r < 32; ++r) a[r] = sb[swz((r << 5) | t)];

    // X in-register wires 0..3 in LA (partners r^0x18, r^0xC, r^6, r^3), half-sums.
    u64 X0 = 0, X1 = 0, X2 = 0, X3 = 0;
#pragma unroll
    for (int r = 0; r < 32; ++r) {
        if (!(r & 0x10)) X0 = f2fma(a[r], a[r ^ 0x18], X0);
        if (!(r & 0x08)) X1 = f2fma(a[r], a[r ^ 0x0C], X1);
        if (!(r & 0x04)) X2 = f2fma(a[r], a[r ^ 0x06], X2);
        if (!(r & 0x02)) X3 = f2fma(a[r], a[r ^ 0x03], X3);
    }
    const float x0 = hadd(X0), x1 = hadd(X1), x2 = hadd(X2), x3 = hadd(X3);

    // Thread-parity signs for the Z parts (t-masks from M_b >> 5).
    const float sgA = (__popc(t & 0x0F) & 1) ? -1.f : 1.f;   // wire 0
    const float sgB = (__popc(t & 0x18) & 1) ? -1.f : 1.f;   // wire 1
    const float sgC = (__popc(t & 0x1C) & 1) ? -1.f : 1.f;   // wire 2
    const float sgD = (__popc(t & 0x1E) & 1) ? -1.f : 1.f;   // wire 3
    const float sgE = (__popc(t & 0x1F) & 1) ? -1.f : 1.f;   // wires 4..9

    // Combine: E_q = cz[q] * Z_q + cxw[q] * X_q  (per-thread partials).
    float e[NW];
    e[0] = cz[0] * (sgA * s1F)   + cxw[0] * x0;
    e[1] = cz[1] * (sgB * tot_s) + cxw[1] * x1;
    e[2] = cz[2] * (sgC * tot_s) + cxw[2] * x2;
    e[3] = cz[3] * (sgD * tot_s) + cxw[3] * x3;
    e[4] = cz[4] * (sgE * tot_s) + cxw[4] * x4;
    e[5] = cz[5] * (sgE * s10)   + cxw[5] * x5;
    e[6] = cz[6] * (sgE * s18)   + cxw[6] * x6;
    e[7] = cz[7] * (sgE * s1C)   + cxw[7] * x7;
    e[8] = cz[8] * (sgE * s1E)   + cxw[8] * x8;
    e[9] = cz[9] * (sgE * s1F)   + cxw[9] * x9;

    // Packed warp reduction of 10 values as 5 u64.
    u64 vp[5];
#pragma unroll
    for (int j = 0; j < 5; ++j) vp[j] = pk(e[2 * j], e[2 * j + 1]);
#pragma unroll
    for (int off = 16; off; off >>= 1) {
#pragma unroll
        for (int j = 0; j < 5; ++j)
            vp[j] = f2add(vp[j], __shfl_xor_sync(0xffffffffu, vp[j], off));
    }
    if (t == 0) {
#pragma unroll
        for (int j = 0; j < 5; ++j) {
            float vx, vy;
            upk(vp[j], vx, vy);
            out[(size_t)n * NW + 2 * j]     = vx;
            out[(size_t)n * NW + 2 * j + 1] = vy;
        }
    }
}

extern "C" void kernel_launch(void* const* d_in, const int* in_sizes, int n_in,
                              void* d_out, int out_size) {
    const float* x   = (const float*)d_in[0];
    const float* rx0 = (const float*)d_in[1];
    const float* ry0 = (const float*)d_in[2];
    const float* ry1 = (const float*)d_in[3];
    float* out = (float*)d_out;
    const int n_states = in_sizes[0] / DIM;            // 4096
    qsa_prep<<<1, 32>>>(rx0, ry0, ry1);
    qsa11_kernel<<<n_states / WARPS_PER_BLK, 32 * WARPS_PER_BLK>>>(x, out);
}

// round 13
// speedup vs baseline: 1.2155x; 1.0729x over previous
#include <cuda_runtime.h>

#define NW 10
#define DIM 1024
#define WARPS_PER_BLK 4

typedef unsigned long long u64;

// ---- packed f32x2 primitives ----
__device__ __forceinline__ u64 pk(float x, float y) {
    u64 r; asm("mov.b64 %0,{%1,%2};" : "=l"(r) : "f"(x), "f"(y)); return r;
}
__device__ __forceinline__ u64 pkb(float x) { return pk(x, x); }
__device__ __forceinline__ void upk(u64 a, float& x, float& y) {
    asm("mov.b64 {%0,%1},%2;" : "=f"(x), "=f"(y) : "l"(a));
}
__device__ __forceinline__ float hadd(u64 a) {
    float x, y; upk(a, x, y); return x + y;
}
__device__ __forceinline__ u64 f2fma(u64 a, u64 b, u64 c) {
    u64 d; asm("fma.rn.f32x2 %0,%1,%2,%3;" : "=l"(d) : "l"(a), "l"(b), "l"(c)); return d;
}
__device__ __forceinline__ u64 f2mul(u64 a, u64 b) {
    u64 d; asm("mul.rn.f32x2 %0,%1,%2;" : "=l"(d) : "l"(a), "l"(b)); return d;
}
__device__ __forceinline__ u64 f2add(u64 a, u64 b) {
    u64 d; asm("add.rn.f32x2 %0,%1,%2;" : "=l"(d) : "l"(a), "l"(b)); return d;
}
__device__ __forceinline__ u64 f2sub(u64 a, u64 b) {
    u64 d; asm("sub.rn.f32x2 %0,%1,%2;" : "=l"(d) : "l"(a), "l"(b)); return d;
}
__device__ __forceinline__ u64 swp(u64 a) {      // (x,y)->(y,x)
    float x, y; upk(a, x, y); return pk(y, x);
}
__device__ __forceinline__ u64 ldsv(const u64* p) {   // no cross-gate hoisting
    return *(const volatile u64*)p;
}

// XOR swizzle for conflict-free 32x32 8-byte transpose through shared memory.
__device__ __forceinline__ int swz(int idx) {
    return (idx & 0x3E0) | (((idx >> 5) ^ idx) & 31);
}

// Real RY butterfly on register bit K (packed complex amplitudes).
template<int K>
__device__ __forceinline__ void ryg(u64* a, const u64* cf) {
    const u64 cc = ldsv(cf + 0), ss = ldsv(cf + 1), nss = ldsv(cf + 2);
#pragma unroll
    for (int p = 0; p < 16; ++p) {
        const int m0 = ((p >> K) << (K + 1)) | (p & ((1 << K) - 1));
        const int m1 = m0 | (1 << K);
        u64 n0 = f2fma(cc, a[m0], f2mul(nss, a[m1]));
        u64 n1 = f2fma(ss, a[m0], f2mul(cc,  a[m1]));
        a[m0] = n0; a[m1] = n1;
    }
}

// ============================================================================
// Layer 1 ZYZ-factored: layer1 = Dphi * (prod_q RY_q) * Dlam (Dlam at load,
// Dphi applied in LB). Layer-2 RY + CNOT folded into observables (R7).
// Per-block prep is overlapped with the state LDGs (issued first).
// ============================================================================

__global__ __launch_bounds__(128, 4)
void qsa12_kernel(const float* __restrict__ x,
                  const float* __restrict__ rx0,
                  const float* __restrict__ ry0,
                  const float* __restrict__ ry1,
                  float* __restrict__ out)
{
    __shared__ u64 buf[WARPS_PER_BLK][DIM];   // 8 KB per warp
    __shared__ u64 cry[NW][3];
    __shared__ u64 lamR[32], lamT[32], phiT[32], phiRc[32], phiRs[32];
    __shared__ float sphi[NW], slam[NW];
    __shared__ float cz[NW], cxw[NW];

    const int tid = threadIdx.x;
    const int w = tid >> 5;
    const int t = tid & 31;
    const int n = blockIdx.x * WARPS_PER_BLK + w;   // state 0..4095
    u64* sb = buf[w];

    // ---- Issue state loads FIRST (LA: i=(r<<5)|t); prep overlaps the latency ----
    u64 a[32];
    const float* xr = x + (size_t)n * DIM;
#pragma unroll
    for (int r = 0; r < 32; ++r) a[r] = pkb(xr[(r << 5) + t]);

    // ---- Prep stage 1 (10 threads): ZYZ decomposition ----
    if (tid < NW) {
        float s, c, s0, c0, s1, c1;
        sincosf(0.5f * rx0[tid], &s,  &c);
        sincosf(0.5f * ry0[tid], &s0, &c0);
        sincosf(0.5f * ry1[tid], &s1, &c1);
        // M = RY(ry0)*RX(rx0) = [[a, b], [-conj(b), conj(a)]]
        const float ar =  c0 * c;
        const float ai =  s0 * s;
        const float br = -s0 * c;
        const float bi = -c0 * s;
        // ZYZ: M = RZ(phi) RY(2T) RZ(lam) (conventions validated in R10/R11)
        const float uu = atan2f(ai, ar);
        const float vv = atan2f(-bi, -br);
        sphi[tid] = -(uu + vv);
        slam[tid] = vv - uu;
        const float cT = sqrtf(ar * ar + ai * ai);
        const float sT = sqrtf(br * br + bi * bi);
        cry[tid][0] = pkb(cT);
        cry[tid][1] = pkb(sT);
        cry[tid][2] = pkb(-sT);
        cz[tid]  = c1 * c1 - s1 * s1;
        cxw[tid] = -4.f * c1 * s1;       // half-sum X accumulation
    }
    __syncthreads();

    // ---- Prep stage 2: one table per warp, one sincosf per lane ----
    {
        float ang = 0.f;
        if (w == 0 || w == 2) {          // wires 0-4 pattern over 5-bit index t
            const float* src = (w == 0) ? slam : sphi;
#pragma unroll
            for (int k = 0; k < 5; ++k) if ((t >> (4 - k)) & 1) ang += src[k];
        } else {                          // wires 5-9 pattern
            const float* src = (w == 1) ? slam : sphi;
#pragma unroll
            for (int k = 5; k < 10; ++k) if ((t >> (9 - k)) & 1) ang += src[k];
        }
        float sa, ca;
        sincosf(ang, &sa, &ca);
        if      (w == 0) lamR[t] = pk(ca, sa);
        else if (w == 1) lamT[t] = pk(ca, sa);
        else if (w == 2) phiT[t] = pk(ca, sa);
        else { phiRc[t] = pkb(ca); phiRs[t] = pk(-sa, sa); }
    }
    __syncthreads();

    // ---- Sum of squares (loads have landed) ----
    u64 sq = 0ull;
#pragma unroll
    for (int r = 0; r < 32; ++r) sq = f2fma(a[r], a[r], sq);
    float sumsq, dmy;
    upk(sq, sumsq, dmy);
#pragma unroll
    for (int off = 16; off; off >>= 1)
        sumsq += __shfl_xor_sync(0xffffffffu, sumsq, off);
    const float inv = 1.f / fmaxf(sqrtf(sumsq), 1e-12f);

    // ---- Init: a[i] = v * inv * e^{i lam(i)}  (input real -> plain mul) ----
    {
        float ct, st;
        upk(lamT[t], ct, st);
        const u64 T1 = pkb(ct * inv);
        const u64 T2 = pk(-st * inv, st * inv);
#pragma unroll
        for (int r = 0; r < 32; ++r) {
            u64 z = ldsv(lamR + r);
            a[r] = f2mul(a[r], f2fma(z, T1, f2mul(swp(z), T2)));
        }
    }

    // ---- Phase A: RY on wires 0..4 (wire q -> reg bit K=4-q) ----
    ryg<4>(a, cry[0]);
    ryg<3>(a, cry[1]);
    ryg<2>(a, cry[2]);
    ryg<1>(a, cry[3]);
    ryg<0>(a, cry[4]);

    // ---- Remap LA -> LB (transpose) ----
    __syncwarp();
#pragma unroll
    for (int r = 0; r < 32; ++r) sb[swz((r << 5) | t)] = a[r];
    __syncwarp();
#pragma unroll
    for (int r = 0; r < 32; ++r) a[r] = sb[swz((t << 5) | r)];

    // ---- Phase B: RY on wires 5..9 (wire q -> reg bit K=9-q) ----
    ryg<4>(a, cry[5]);
    ryg<3>(a, cry[6]);
    ryg<2>(a, cry[7]);
    ryg<1>(a, cry[8]);
    ryg<0>(a, cry[9]);

    // ---- Apply Dphi (separable in LB: t-part wires 0-4, r-part wires 5-9) ----
    {
        float cpt, spt;
        upk(phiT[t], cpt, spt);
        const u64 T1b = pkb(cpt);
        const u64 T2b = pk(-spt, spt);
#pragma unroll
        for (int r = 0; r < 32; ++r) {
            u64 v = f2fma(a[r], ldsv(phiRc + r), f2mul(swp(a[r]), ldsv(phiRs + r)));
            a[r] = f2fma(v, T1b, f2mul(swp(v), T2b));
        }
    }

    // ======================= Epilogue on psi (LB: j=(t<<5)|r) ================
    // (identical to the validated R9/R11 epilogue)

    // Z-part: tot + 5 signed r-sums via quad butterflies.
    u64 tot = 0, S10 = 0, S18 = 0, S1C = 0, S1E = 0, S1F = 0;
#pragma unroll
    for (int r = 0; r < 32; r += 4) {
        u64 q0 = f2mul(a[r],     a[r]);
        u64 q1 = f2mul(a[r + 1], a[r + 1]);
        u64 q2 = f2mul(a[r + 2], a[r + 2]);
        u64 q3 = f2mul(a[r + 3], a[r + 3]);
        u64 s01 = f2add(q0, q1), s23 = f2add(q2, q3);
        u64 d01 = f2sub(q0, q1), d23 = f2sub(q2, q3);
        u64 ss = f2add(s01, s23);
        u64 sd = f2sub(s01, s23);
        u64 df = f2sub(d01, d23);
        const int pq = ((r >> 4) ^ (r >> 3) ^ (r >> 2)) & 1;
        tot = f2add(tot, ss);
        S10 = (r & 0x10)                  ? f2sub(S10, ss) : f2add(S10, ss);
        S18 = (((r >> 4) ^ (r >> 3)) & 1) ? f2sub(S18, ss) : f2add(S18, ss);
        S1C = pq ? f2sub(S1C, ss) : f2add(S1C, ss);
        S1E = pq ? f2sub(S1E, sd) : f2add(S1E, sd);
        S1F = pq ? f2sub(S1F, df) : f2add(S1F, df);
    }
    const float tot_s = hadd(tot);
    const float s10 = hadd(S10), s18 = hadd(S18), s1C = hadd(S1C);
    const float s1E = hadd(S1E), s1F = hadd(S1F);

    // X in-register wires 5..8 (partners r^0x18, r^0xC, r^6, r^3), half-sums.
    u64 X5 = 0, X6 = 0, X7 = 0, X8 = 0;
#pragma unroll
    for (int r = 0; r < 32; ++r) {
        if (!(r & 0x10)) X5 = f2fma(a[r], a[r ^ 0x18], X5);
        if (!(r & 0x08)) X6 = f2fma(a[r], a[r ^ 0x0C], X6);
        if (!(r & 0x04)) X7 = f2fma(a[r], a[r ^ 0x06], X7);
        if (!(r & 0x02)) X8 = f2fma(a[r], a[r ^ 0x03], X8);
    }
    const float x5 = hadd(X5), x6 = hadd(X6), x7 = hadd(X7), x8 = hadd(X8);

    // Straddler X wires, half-sums:
    //  w4 (m=0x30): pairs (t, r<16) <-> (t^1, r+16)
    //  w9 (m=0x301): pairs (t, r even) <-> (t^0x18, r+1)
    u64 X4 = 0, X9 = 0;
#pragma unroll
    for (int r = 0; r < 16; ++r) {
        u64 p4 = __shfl_xor_sync(0xffffffffu, a[r + 16], 1);
        X4 = f2fma(a[r], p4, X4);
    }
#pragma unroll
    for (int r = 0; r < 32; r += 2) {
        u64 p9 = __shfl_xor_sync(0xffffffffu, a[r + 1], 0x18);
        X9 = f2fma(a[r], p9, X9);
    }
    const float x4 = hadd(X4), x9 = hadd(X9);

    // ---- Transpose LB -> LA for wires 0..3 X-terms ----
    __syncwarp();
#pragma unroll
    for (int r = 0; r < 32; ++r) sb[swz((t << 5) | r)] = a[r];
    __syncwarp();
#pragma unroll
    for (int r = 0; r < 32; ++r) a[r] = sb[swz((r << 5) | t)];

    // X in-register wires 0..3 in LA (partners r^0x18, r^0xC, r^6, r^3), half-sums.
    u64 X0 = 0, X1 = 0, X2 = 0, X3 = 0;
#pragma unroll
    for (int r = 0; r < 32; ++r) {
        if (!(r & 0x10)) X0 = f2fma(a[r], a[r ^ 0x18], X0);
        if (!(r & 0x08)) X1 = f2fma(a[r], a[r ^ 0x0C], X1);
        if (!(r & 0x04)) X2 = f2fma(a[r], a[r ^ 0x06], X2);
        if (!(r & 0x02)) X3 = f2fma(a[r], a[r ^ 0x03], X3);
    }
    const float x0 = hadd(X0), x1 = hadd(X1), x2 = hadd(X2), x3 = hadd(X3);

    // Thread-parity signs for the Z parts (t-masks from M_b >> 5).
    const float sgA = (__popc(t & 0x0F) & 1) ? -1.f : 1.f;   // wire 0
    const float sgB = (__popc(t & 0x18) & 1) ? -1.f : 1.f;   // wire 1
    const float sgC = (__popc(t & 0x1C) & 1) ? -1.f : 1.f;   // wire 2
    const float sgD = (__popc(t & 0x1E) & 1) ? -1.f : 1.f;   // wire 3
    const float sgE = (__popc(t & 0x1F) & 1) ? -1.f : 1.f;   // wires 4..9

    // Combine: E_q = cz[q] * Z_q + cxw[q] * X_q  (per-thread partials).
    float e[NW];
    e[0] = cz[0] * (sgA * s1F)   + cxw[0] * x0;
    e[1] = cz[1] * (sgB * tot_s) + cxw[1] * x1;
    e[2] = cz[2] * (sgC * tot_s) + cxw[2] * x2;
    e[3] = cz[3] * (sgD * tot_s) + cxw[3] * x3;
    e[4] = cz[4] * (sgE * tot_s) + cxw[4] * x4;
    e[5] = cz[5] * (sgE * s10)   + cxw[5] * x5;
    e[6] = cz[6] * (sgE * s18)   + cxw[6] * x6;
    e[7] = cz[7] * (sgE * s1C)   + cxw[7] * x7;
    e[8] = cz[8] * (sgE * s1E)   + cxw[8] * x8;
    e[9] = cz[9] * (sgE * s1F)   + cxw[9] * x9;

    // Packed warp reduction of 10 values as 5 u64.
    u64 vp[5];
#pragma unroll
    for (int j = 0; j < 5; ++j) vp[j] = pk(e[2 * j], e[2 * j + 1]);
#pragma unroll
    for (int off = 16; off; off >>= 1) {
#pragma unroll
        for (int j = 0; j < 5; ++j)
            vp[j] = f2add(vp[j], __shfl_xor_sync(0xffffffffu, vp[j], off));
    }
    if (t == 0) {
#pragma unroll
        for (int j = 0; j < 5; ++j) {
            float vx, vy;
            upk(vp[j], vx, vy);
            out[(size_t)n * NW + 2 * j]     = vx;
            out[(size_t)n * NW + 2 * j + 1] = vy;
        }
    }
}

extern "C" void kernel_launch(void* const* d_in, const int* in_sizes, int n_in,
                              void* d_out, int out_size) {
    const float* x   = (const float*)d_in[0];
    const float* rx0 = (const float*)d_in[1];
    const float* ry0 = (const float*)d_in[2];
    const float* ry1 = (const float*)d_in[3];
    float* out = (float*)d_out;
    const int n_states = in_sizes[0] / DIM;            // 4096
    qsa12_kernel<<<n_states / WARPS_PER_BLK, 32 * WARPS_PER_BLK>>>(x, rx0, ry0, ry1, out);
}